// round 5
// baseline (speedup 1.0000x reference)
#include <cuda_runtime.h>
#include <math.h>

// Problem constants
#define B_   128
#define T_   2048
#define H_   200
#define NS_  5

#define BM 64
#define BK 8
#define TILES_PER_B (T_ / BM)           // 32
#define NTILES (B_ * TILES_PER_B)       // 4096

// Scratch (static device globals — no dynamic allocation)
__device__ float g_qproj[B_ * H_];            // q@Wa^T + ba + bua
__device__ float g_ctxpart[NTILES * H_];      // per-tile exp-weighted enc sums
__device__ float g_denpart[NTILES];           // per-tile exp sums
__device__ float g_ctx[B_ * H_];              // normalized context

__device__ __forceinline__ float sigm(float x) { return 1.0f / (1.0f + expf(-x)); }

__device__ __forceinline__ float tanh_fast(float x) {
    float y;
    asm("tanh.approx.f32 %0, %1;" : "=f"(y) : "f"(x));
    return y;
}

__device__ __forceinline__ float warp_sum(float a) {
    #pragma unroll
    for (int o = 16; o > 0; o >>= 1) a += __shfl_xor_sync(0xffffffffu, a, o);
    return a;
}

typedef unsigned long long ull;

__device__ __forceinline__ ull ffma2(ull a, ull b, ull c) {
    ull d;
    asm("fma.rn.f32x2 %0, %1, %2, %3;" : "=l"(d) : "l"(a), "l"(b), "l"(c));
    return d;
}
__device__ __forceinline__ ull dup2(float x) {
    ull d;
    asm("mov.b64 %0, {%1, %1};" : "=l"(d) : "f"(x));
    return d;
}
__device__ __forceinline__ float lo2(ull v) { return __uint_as_float((unsigned)(v & 0xffffffffULL)); }
__device__ __forceinline__ float hi2(ull v) { return __uint_as_float((unsigned)(v >> 32)); }

// ---------------------------------------------------------------------------
// K0: q_proj[b][j] = sum_k h0[b][k]*Wa[j][k] + ba[j] + bua[j]
// Warp-cooperative: lanes stride k (coalesced), shfl reduce.
// ---------------------------------------------------------------------------
__global__ __launch_bounds__(256)
void k0_qproj(const float* __restrict__ h0, const float* __restrict__ Wa,
              const float* __restrict__ ba, const float* __restrict__ bua) {
    int b = blockIdx.x, tid = threadIdx.x;
    int wid = tid >> 5, lane = tid & 31;
    __shared__ float hs[H_];
    for (int i = tid; i < H_; i += 256) hs[i] = h0[b * H_ + i];
    __syncthreads();
    #pragma unroll 2
    for (int j = wid; j < H_; j += 8) {
        const float* w = Wa + j * H_;
        float a = 0.f;
        for (int k = lane; k < H_; k += 32) a += hs[k] * w[k];
        a = warp_sum(a);
        if (lane == 0) g_qproj[b * H_ + j] = a + ba[j] + bua[j];
    }
}

// ---------------------------------------------------------------------------
// K1: fused scores + exp + partial context.
//   kp[r][j] = sum_k enc[r][k] * Ua[j][k]
//   score[r] = sum_j Va[j] * tanh(qproj[b][j] + kp[r][j])
//   e[r] = exp(score[r])           (no max subtraction: |score| <= ||Va||_1)
//   ctxpart[tile][k] = sum_r e[r] * enc[r][k] ; denpart[tile] = sum_r e[r]
// ---------------------------------------------------------------------------
__global__ __launch_bounds__(256, 2)
void k1_scores(const float* __restrict__ enc, const float* __restrict__ Ua,
               const float* __restrict__ Va) {
    __shared__ float enc_s[BK][BM];     // [k][row]
    __shared__ float ua_s[BK][H_];      // [k][j]
    __shared__ float qp_s[H_];
    __shared__ float va_s[H_];
    __shared__ float red[BM][26];
    __shared__ float es[BM];

    int tid = threadIdx.x;
    int row0 = blockIdx.x * BM;
    int b = row0 >> 11;                 // T_ = 2048
    const float* encB = enc + (size_t)row0 * H_;

    for (int i = tid; i < H_; i += 256) {
        qp_s[i] = g_qproj[b * H_ + i];
        va_s[i] = Va[i];
    }

    int tx = tid % 25;
    int ty = tid / 25;
    bool compute = (tid < 200);

    ull acc2[8][4];
    #pragma unroll
    for (int i = 0; i < 8; i++)
        #pragma unroll
        for (int p = 0; p < 4; p++) acc2[i][p] = 0ULL;

    // enc tile load: 64 rows x 8 k = 256 float2, one per thread.
    int lr = tid >> 2;                  // row 0..63
    int lk = (tid & 3) * 2;             // k offset 0,2,4,6

    for (int k0 = 0; k0 < H_; k0 += BK) {
        {
            float2 v = *(const float2*)(encB + lr * H_ + k0 + lk);
            enc_s[lk + 0][lr] = v.x;
            enc_s[lk + 1][lr] = v.y;
        }
        if (tid < 200) {
            const float* u = Ua + tid * H_ + k0;
            float4 v0 = *(const float4*)(u);
            float4 v1 = *(const float4*)(u + 4);
            ua_s[0][tid] = v0.x; ua_s[1][tid] = v0.y;
            ua_s[2][tid] = v0.z; ua_s[3][tid] = v0.w;
            ua_s[4][tid] = v1.x; ua_s[5][tid] = v1.y;
            ua_s[6][tid] = v1.z; ua_s[7][tid] = v1.w;
        }
        __syncthreads();
        if (compute) {
            #pragma unroll
            for (int kk = 0; kk < BK; kk++) {
                ull a2[8], b2[4];
                // A: 4x LDS.64 (row pairs) + packs
                #pragma unroll
                for (int q = 0; q < 4; q++) {
                    float2 ar = *(const float2*)&enc_s[kk][ty * 8 + q * 2];
                    a2[q * 2 + 0] = dup2(ar.x);
                    a2[q * 2 + 1] = dup2(ar.y);
                }
                {
                    float2 p0 = *(const float2*)&ua_s[kk][tx * 4];
                    float2 p1 = *(const float2*)&ua_s[kk][tx * 4 + 2];
                    float2 p2 = *(const float2*)&ua_s[kk][100 + tx * 4];
                    float2 p3 = *(const float2*)&ua_s[kk][100 + tx * 4 + 2];
                    b2[0] = *(const ull*)&p0;
                    b2[1] = *(const ull*)&p1;
                    b2[2] = *(const ull*)&p2;
                    b2[3] = *(const ull*)&p3;
                }
                #pragma unroll
                for (int i = 0; i < 8; i++)
                    #pragma unroll
                    for (int p = 0; p < 4; p++)
                        acc2[i][p] = ffma2(a2[i], b2[p], acc2[i][p]);
            }
        }
        __syncthreads();
    }

    // Epilogue 1: tanh + Va-weighted reduction over j -> scores
    if (compute) {
        float part[8];
        #pragma unroll
        for (int i = 0; i < 8; i++) part[i] = 0.f;
        #pragma unroll
        for (int p = 0; p < 4; p++) {
            int j0 = (p < 2) ? (tx * 4 + p * 2) : (100 + tx * 4 + (p - 2) * 2);
            float qlo = qp_s[j0],     vlo = va_s[j0];
            float qhi = qp_s[j0 + 1], vhi = va_s[j0 + 1];
            #pragma unroll
            for (int i = 0; i < 8; i++) {
                part[i] += vlo * tanh_fast(qlo + lo2(acc2[i][p]));
                part[i] += vhi * tanh_fast(qhi + hi2(acc2[i][p]));
            }
        }
        #pragma unroll
        for (int i = 0; i < 8; i++) red[ty * 8 + i][tx] = part[i];
    }
    __syncthreads();
    if (tid < BM) {
        float s = 0.f;
        #pragma unroll
        for (int t = 0; t < 25; t++) s += red[tid][t];
        es[tid] = expf(s);
    }
    __syncthreads();

    // Epilogue 2: partial context (re-read enc tile; L2-hot) + denom
    if (tid < H_) {
        const float* e = encB + tid;
        float a0 = 0.f, a1 = 0.f, a2 = 0.f, a3 = 0.f;
        #pragma unroll 4
        for (int r = 0; r < BM; r += 4) {
            a0 += es[r + 0] * e[(r + 0) * H_];
            a1 += es[r + 1] * e[(r + 1) * H_];
            a2 += es[r + 2] * e[(r + 2) * H_];
            a3 += es[r + 3] * e[(r + 3) * H_];
        }
        g_ctxpart[blockIdx.x * H_ + tid] = (a0 + a1) + (a2 + a3);
    } else if (tid == 224) {
        float s = 0.f;
        #pragma unroll 8
        for (int r = 0; r < BM; r++) s += es[r];
        g_denpart[blockIdx.x] = s;
    }
}

// ---------------------------------------------------------------------------
// K2: reduce partials -> normalized context. One block per batch.
// ---------------------------------------------------------------------------
__global__ void k2_reduce() {
    int b = blockIdx.x, tid = threadIdx.x;
    __shared__ float dsum;
    if (tid == 0) {
        float s = 0.f;
        #pragma unroll
        for (int t = 0; t < TILES_PER_B; t++) s += g_denpart[b * TILES_PER_B + t];
        dsum = 1.0f / s;
    }
    __syncthreads();
    if (tid < H_) {
        float a = 0.f;
        #pragma unroll
        for (int t = 0; t < TILES_PER_B; t++)
            a += g_ctxpart[(b * TILES_PER_B + t) * H_ + tid];
        g_ctx[b * H_ + tid] = a * dsum;
    }
}

// ---------------------------------------------------------------------------
// K4: decode. One block per batch. All row-dot-products are warp-cooperative
// (lanes stride k -> coalesced LDG, shfl reduce) to avoid the L1tex
// 32-wavefront penalty of per-thread row loops.
// ---------------------------------------------------------------------------
__global__ __launch_bounds__(256)
void k4_decode(const float* __restrict__ x_in, const float* __restrict__ h0,
               const float* __restrict__ c0,
               const float* __restrict__ W_ih, const float* __restrict__ W_hh,
               const float* __restrict__ b_ih, const float* __restrict__ b_hh,
               const float* __restrict__ W1, const float* __restrict__ b1,
               const float* __restrict__ W2, const float* __restrict__ b2,
               const float* __restrict__ W3, const float* __restrict__ b3,
               float* __restrict__ out) {
    int b = blockIdx.x, tid = threadIdx.x;
    int wid = tid >> 5, lane = tid & 31;
    __shared__ float ctx[H_], h0s[H_], c0s[H_];
    __shared__ float gb[4 * H_], wcol[4 * H_], gbias[4 * H_];
    __shared__ float hr[H_], o1[100], o2[52];
    __shared__ float b1s[100], b2s[52], w3s[52];
    __shared__ float xs;

    for (int i = tid; i < H_; i += 256) {
        ctx[i] = g_ctx[b * H_ + i];
        h0s[i] = h0[b * H_ + i];
        c0s[i] = c0[b * H_ + i];
    }
    for (int j = tid; j < 4 * H_; j += 256) gbias[j] = b_ih[j] + b_hh[j];
    if (tid < 100) b1s[tid] = b1[tid];
    if (tid < 50)  b2s[tid] = b2[tid];
    if (tid < 50)  w3s[tid] = W3[tid];
    if (tid == 0)  xs = x_in[b];
    __syncthreads();

    // gates_base[j] = gbias[j] + h0 @ W_hh[j] + ctx @ W_ih[j][1:]
    #pragma unroll 2
    for (int j = wid; j < 4 * H_; j += 8) {
        const float* whh = W_hh + j * H_;
        const float* wih = W_ih + j * (H_ + 1) + 1;
        float a = 0.f;
        for (int k = lane; k < H_; k += 32) a += h0s[k] * whh[k] + ctx[k] * wih[k];
        a = warp_sum(a);
        if (lane == 0) { gb[j] = a + gbias[j]; wcol[j] = wih[-1]; }
    }
    __syncthreads();

    for (int s = 0; s < NS_; s++) {
        float x = xs;
        if (tid < H_) {
            int j = tid;
            float gi = gb[j]           + x * wcol[j];
            float gf = gb[H_ + j]      + x * wcol[H_ + j];
            float gg = gb[2 * H_ + j]  + x * wcol[2 * H_ + j];
            float go = gb[3 * H_ + j]  + x * wcol[3 * H_ + j];
            float c = sigm(gf) * c0s[j] + sigm(gi) * tanhf(gg);
            float h = sigm(go) * tanhf(c);
            hr[j] = fmaxf(h, 0.f);
        }
        __syncthreads();
        #pragma unroll 2
        for (int j = wid; j < 100; j += 8) {
            const float* w = W1 + j * H_;
            float a = 0.f;
            for (int k = lane; k < H_; k += 32) a += w[k] * hr[k];
            a = warp_sum(a);
            if (lane == 0) o1[j] = fmaxf(a + b1s[j], 0.f);
        }
        __syncthreads();
        #pragma unroll 2
        for (int j = wid; j < 50; j += 8) {
            const float* w = W2 + j * 100;
            float a = 0.f;
            for (int k = lane; k < 100; k += 32) a += w[k] * o1[k];
            a = warp_sum(a);
            if (lane == 0) o2[j] = fmaxf(a + b2s[j], 0.f);
        }
        __syncthreads();
        if (wid == 0) {
            float a = 0.f;
            for (int k = lane; k < 50; k += 32) a += w3s[k] * o2[k];
            a = warp_sum(a);
            if (lane == 0) {
                float y = a + b3[0];
                out[b * NS_ + s] = y;
                xs = y;
            }
        }
        __syncthreads();
    }
}

// ---------------------------------------------------------------------------
extern "C" void kernel_launch(void* const* d_in, const int* in_sizes, int n_in,
                              void* d_out, int out_size) {
    const float* x    = (const float*)d_in[0];
    const float* h0   = (const float*)d_in[1];
    const float* c0   = (const float*)d_in[2];
    const float* enc  = (const float*)d_in[3];
    const float* Wa   = (const float*)d_in[4];
    const float* ba   = (const float*)d_in[5];
    const float* Ua   = (const float*)d_in[6];
    const float* bua  = (const float*)d_in[7];
    const float* Va   = (const float*)d_in[8];
    // d_in[9] = bva: constant shift of scores, softmax-invariant -> unused.
    const float* W_ih = (const float*)d_in[10];
    const float* W_hh = (const float*)d_in[11];
    const float* b_ih = (const float*)d_in[12];
    const float* b_hh = (const float*)d_in[13];
    const float* W1   = (const float*)d_in[14];
    const float* b1   = (const float*)d_in[15];
    const float* W2   = (const float*)d_in[16];
    const float* b2   = (const float*)d_in[17];
    const float* W3   = (const float*)d_in[18];
    const float* b3   = (const float*)d_in[19];
    float* out = (float*)d_out;

    k0_qproj<<<B_, 256>>>(h0, Wa, ba, bua);
    k1_scores<<<NTILES, 256>>>(enc, Ua, Va);
    k2_reduce<<<B_, 256>>>();
    k4_decode<<<B_, 256>>>(x, h0, c0, W_ih, W_hh, b_ih, b_hh,
                           W1, b1, W2, b2, W3, b3, out);
}

// round 9
// speedup vs baseline: 1.4914x; 1.4914x over previous
#include <cuda_runtime.h>
#include <math.h>

// Problem constants
#define B_   128
#define T_   2048
#define H_   200
#define NS_  5

#define BM 64
#define BK 8
#define TILES_PER_B (T_ / BM)           // 32
#define NTILES (B_ * TILES_PER_B)       // 4096

// Scratch (static device globals — no dynamic allocation)
__device__ float g_qproj[B_ * H_];            // q@Wa^T + ba + bua
__device__ float g_ctxpart[NTILES * H_];      // per-tile exp-weighted enc sums
__device__ float g_denpart[NTILES];           // per-tile exp sums
__device__ float g_ctx[B_ * H_];              // normalized context
__device__ float g_gates[B_ * 4 * H_];        // gates_base per (b, j)
__device__ float g_wcol[4 * H_];              // W_ih[:,0]

__device__ __forceinline__ float sigm(float x) { return 1.0f / (1.0f + expf(-x)); }

__device__ __forceinline__ float tanh_fast(float x) {
    float y;
    asm("tanh.approx.f32 %0, %1;" : "=f"(y) : "f"(x));
    return y;
}

__device__ __forceinline__ float warp_sum(float a) {
    #pragma unroll
    for (int o = 16; o > 0; o >>= 1) a += __shfl_xor_sync(0xffffffffu, a, o);
    return a;
}

typedef unsigned long long ull;

__device__ __forceinline__ ull ffma2(ull a, ull b, ull c) {
    ull d;
    asm("fma.rn.f32x2 %0, %1, %2, %3;" : "=l"(d) : "l"(a), "l"(b), "l"(c));
    return d;
}
__device__ __forceinline__ ull dup2(float x) {
    ull d;
    asm("mov.b64 %0, {%1, %1};" : "=l"(d) : "f"(x));
    return d;
}
__device__ __forceinline__ float lo2(ull v) { return __uint_as_float((unsigned)(v & 0xffffffffULL)); }
__device__ __forceinline__ float hi2(ull v) { return __uint_as_float((unsigned)(v >> 32)); }

// ---------------------------------------------------------------------------
// K0: q_proj[b][j] = sum_k h0[b][k]*Wa[j][k] + ba[j] + bua[j]
// ---------------------------------------------------------------------------
__global__ __launch_bounds__(256)
void k0_qproj(const float* __restrict__ h0, const float* __restrict__ Wa,
              const float* __restrict__ ba, const float* __restrict__ bua) {
    int b = blockIdx.x, tid = threadIdx.x;
    int wid = tid >> 5, lane = tid & 31;
    __shared__ float hs[H_];
    for (int i = tid; i < H_; i += 256) hs[i] = h0[b * H_ + i];
    __syncthreads();
    #pragma unroll 2
    for (int j = wid; j < H_; j += 8) {
        const float* w = Wa + j * H_;
        float a = 0.f;
        for (int k = lane; k < H_; k += 32) a += hs[k] * w[k];
        a = warp_sum(a);
        if (lane == 0) g_qproj[b * H_ + j] = a + ba[j] + bua[j];
    }
}

// ---------------------------------------------------------------------------
// K1: fused scores + exp + partial context. (R3 inner loop — scalar A reads.)
// ---------------------------------------------------------------------------
__global__ __launch_bounds__(256, 2)
void k1_scores(const float* __restrict__ enc, const float* __restrict__ Ua,
               const float* __restrict__ Va) {
    __shared__ float enc_s[BK][BM];     // [k][row]
    __shared__ float ua_s[BK][H_];      // [k][j]
    __shared__ float qp_s[H_];
    __shared__ float va_s[H_];
    __shared__ float red[BM][26];
    __shared__ float es[BM];

    int tid = threadIdx.x;
    int row0 = blockIdx.x * BM;
    int b = row0 >> 11;                 // T_ = 2048
    const float* encB = enc + (size_t)row0 * H_;

    for (int i = tid; i < H_; i += 256) {
        qp_s[i] = g_qproj[b * H_ + i];
        va_s[i] = Va[i];
    }

    int tx = tid % 25;
    int ty = tid / 25;
    bool compute = (tid < 200);

    ull acc2[8][4];
    #pragma unroll
    for (int i = 0; i < 8; i++)
        #pragma unroll
        for (int p = 0; p < 4; p++) acc2[i][p] = 0ULL;

    int lr = tid >> 2;                  // row 0..63
    int lk = (tid & 3) * 2;             // k offset 0,2,4,6

    for (int k0 = 0; k0 < H_; k0 += BK) {
        {
            float2 v = *(const float2*)(encB + lr * H_ + k0 + lk);
            enc_s[lk + 0][lr] = v.x;
            enc_s[lk + 1][lr] = v.y;
        }
        if (tid < 200) {
            const float* u = Ua + tid * H_ + k0;
            float4 v0 = *(const float4*)(u);
            float4 v1 = *(const float4*)(u + 4);
            ua_s[0][tid] = v0.x; ua_s[1][tid] = v0.y;
            ua_s[2][tid] = v0.z; ua_s[3][tid] = v0.w;
            ua_s[4][tid] = v1.x; ua_s[5][tid] = v1.y;
            ua_s[6][tid] = v1.z; ua_s[7][tid] = v1.w;
        }
        __syncthreads();
        if (compute) {
            #pragma unroll
            for (int kk = 0; kk < BK; kk++) {
                ull a2[8], b2[4];
                #pragma unroll
                for (int i = 0; i < 8; i++) a2[i] = dup2(enc_s[kk][ty * 8 + i]);
                {
                    float2 p0 = *(const float2*)&ua_s[kk][tx * 4];
                    float2 p1 = *(const float2*)&ua_s[kk][tx * 4 + 2];
                    float2 p2 = *(const float2*)&ua_s[kk][100 + tx * 4];
                    float2 p3 = *(const float2*)&ua_s[kk][100 + tx * 4 + 2];
                    b2[0] = *(const ull*)&p0;
                    b2[1] = *(const ull*)&p1;
                    b2[2] = *(const ull*)&p2;
                    b2[3] = *(const ull*)&p3;
                }
                #pragma unroll
                for (int i = 0; i < 8; i++)
                    #pragma unroll
                    for (int p = 0; p < 4; p++)
                        acc2[i][p] = ffma2(a2[i], b2[p], acc2[i][p]);
            }
        }
        __syncthreads();
    }

    if (compute) {
        float part[8];
        #pragma unroll
        for (int i = 0; i < 8; i++) part[i] = 0.f;
        #pragma unroll
        for (int p = 0; p < 4; p++) {
            int j0 = (p < 2) ? (tx * 4 + p * 2) : (100 + tx * 4 + (p - 2) * 2);
            float qlo = qp_s[j0],     vlo = va_s[j0];
            float qhi = qp_s[j0 + 1], vhi = va_s[j0 + 1];
            #pragma unroll
            for (int i = 0; i < 8; i++) {
                part[i] += vlo * tanh_fast(qlo + lo2(acc2[i][p]));
                part[i] += vhi * tanh_fast(qhi + hi2(acc2[i][p]));
            }
        }
        #pragma unroll
        for (int i = 0; i < 8; i++) red[ty * 8 + i][tx] = part[i];
    }
    __syncthreads();
    if (tid < BM) {
        float s = 0.f;
        #pragma unroll
        for (int t = 0; t < 25; t++) s += red[tid][t];
        es[tid] = expf(s);
    }
    __syncthreads();

    if (tid < H_) {
        const float* e = encB + tid;
        float a0 = 0.f, a1 = 0.f, a2 = 0.f, a3 = 0.f;
        #pragma unroll 4
        for (int r = 0; r < BM; r += 4) {
            a0 += es[r + 0] * e[(r + 0) * H_];
            a1 += es[r + 1] * e[(r + 1) * H_];
            a2 += es[r + 2] * e[(r + 2) * H_];
            a3 += es[r + 3] * e[(r + 3) * H_];
        }
        g_ctxpart[blockIdx.x * H_ + tid] = (a0 + a1) + (a2 + a3);
    } else if (tid == 224) {
        float s = 0.f;
        #pragma unroll 8
        for (int r = 0; r < BM; r++) s += es[r];
        g_denpart[blockIdx.x] = s;
    }
}

// ---------------------------------------------------------------------------
// K2: reduce partials -> normalized context. One block per batch.
// ---------------------------------------------------------------------------
__global__ void k2_reduce() {
    int b = blockIdx.x, tid = threadIdx.x;
    __shared__ float dsum;
    if (tid == 0) {
        float s = 0.f;
        #pragma unroll
        for (int t = 0; t < TILES_PER_B; t++) s += g_denpart[b * TILES_PER_B + t];
        dsum = 1.0f / s;
    }
    __syncthreads();
    if (tid < H_) {
        float a = 0.f;
        #pragma unroll
        for (int t = 0; t < TILES_PER_B; t++)
            a += g_ctxpart[(b * TILES_PER_B + t) * H_ + tid];
        g_ctx[b * H_ + tid] = a * dsum;
    }
}

// ---------------------------------------------------------------------------
// KG: gates GEMM. gb[b][j] = b_ih[j]+b_hh[j] + h0[b]@W_hh[j] + ctx[b]@W_ih[j,1:]
// Grid (4 b-tiles of 32, 100 j-tiles of 8). Thread (jj = tid/32, b = tid%32)
// computes one output over K=400 from smem: X padded to 401 (conflict-free),
// A broadcast per warp. No shfl, no uncoalesced global loads.
// ---------------------------------------------------------------------------
#define KG_XPAD 401
__global__ __launch_bounds__(256)
void kg_gates(const float* __restrict__ h0,
              const float* __restrict__ W_ih, const float* __restrict__ W_hh,
              const float* __restrict__ b_ih, const float* __restrict__ b_hh) {
    extern __shared__ float dsm[];
    float* Xs = dsm;                    // [32][401]
    float* As = dsm + 32 * KG_XPAD;     // [8][400]

    int tid = threadIdx.x;
    int b0 = blockIdx.x * 32;
    int j0 = blockIdx.y * 8;

    // X tile: rows = 32 batches, cols 0:200 = h0, 200:400 = ctx
    for (int idx = tid; idx < 32 * H_; idx += 256) {
        int bb = idx / H_, k = idx % H_;
        Xs[bb * KG_XPAD + k]      = h0[(b0 + bb) * H_ + k];
        Xs[bb * KG_XPAD + H_ + k] = g_ctx[(b0 + bb) * H_ + k];
    }
    // A tile: 8 j rows
    for (int idx = tid; idx < 8 * H_; idx += 256) {
        int jj = idx / H_, k = idx % H_;
        int j = j0 + jj;
        As[jj * 400 + k]      = W_hh[j * H_ + k];
        As[jj * 400 + H_ + k] = W_ih[j * (H_ + 1) + 1 + k];
        if (k == 0 && blockIdx.x == 0) g_wcol[j] = W_ih[j * (H_ + 1)];
    }
    __syncthreads();

    int jj = tid >> 5;                  // 0..7 (warp id -> j)
    int bb = tid & 31;                  // lane -> batch
    int j = j0 + jj;
    const float* a = As + jj * 400;
    const float* xv = Xs + bb * KG_XPAD;
    float acc = b_ih[j] + b_hh[j];
    #pragma unroll 8
    for (int k = 0; k < 400; k++) acc += a[k] * xv[k];
    g_gates[(b0 + bb) * (4 * H_) + j] = acc;
}

// ---------------------------------------------------------------------------
// K4: decode, one block per batch. Gates precomputed by KG. W1/W2 staged in
// dynamic shared with odd padding (conflict-free per-thread row dots).
// ---------------------------------------------------------------------------
#define W1PAD 201
#define W2PAD 101
#define K4_DSM ((100 * W1PAD + 50 * W2PAD) * 4)

__global__ __launch_bounds__(256)
void k4_decode(const float* __restrict__ x_in, const float* __restrict__ c0,
               const float* __restrict__ W1, const float* __restrict__ b1,
               const float* __restrict__ W2, const float* __restrict__ b2,
               const float* __restrict__ W3, const float* __restrict__ b3,
               float* __restrict__ out) {
    extern __shared__ float dsm[];
    float* W1s = dsm;                   // [100][201]
    float* W2s = dsm + 100 * W1PAD;     // [50][101]

    int b = blockIdx.x, tid = threadIdx.x;
    __shared__ float gb[4 * H_], wcol[4 * H_], c0s[H_];
    __shared__ float hr[H_], o1[100], o2[52];
    __shared__ float b1s[100], b2s[52], w3s[52];
    __shared__ float xs;

    for (int j = tid; j < 4 * H_; j += 256) {
        gb[j]   = g_gates[b * (4 * H_) + j];
        wcol[j] = g_wcol[j];
    }
    for (int i = tid; i < H_; i += 256) c0s[i] = c0[b * H_ + i];
    for (int idx = tid; idx < 100 * H_; idx += 256) {
        int r = idx / H_, c = idx % H_;
        W1s[r * W1PAD + c] = W1[idx];
    }
    for (int idx = tid; idx < 50 * 100; idx += 256) {
        int r = idx / 100, c = idx % 100;
        W2s[r * W2PAD + c] = W2[idx];
    }
    if (tid < 100) b1s[tid] = b1[tid];
    if (tid < 50)  b2s[tid] = b2[tid];
    if (tid < 50)  w3s[tid] = W3[tid];
    if (tid == 0)  xs = x_in[b];
    __syncthreads();

    for (int s = 0; s < NS_; s++) {
        float x = xs;
        if (tid < H_) {
            int j = tid;
            float gi = gb[j]           + x * wcol[j];
            float gf = gb[H_ + j]      + x * wcol[H_ + j];
            float gg = gb[2 * H_ + j]  + x * wcol[2 * H_ + j];
            float go = gb[3 * H_ + j]  + x * wcol[3 * H_ + j];
            float c = sigm(gf) * c0s[j] + sigm(gi) * tanhf(gg);
            float h = sigm(go) * tanhf(c);
            hr[j] = fmaxf(h, 0.f);
        }
        __syncthreads();
        if (tid < 100) {
            const float* w = W1s + tid * W1PAD;
            float a = b1s[tid];
            #pragma unroll 8
            for (int k = 0; k < H_; k++) a += w[k] * hr[k];
            o1[tid] = fmaxf(a, 0.f);
        }
        __syncthreads();
        if (tid < 50) {
            const float* w = W2s + tid * W2PAD;
            float a = b2s[tid];
            #pragma unroll 4
            for (int k = 0; k < 100; k++) a += w[k] * o1[k];
            o2[tid] = fmaxf(a, 0.f);
        }
        __syncthreads();
        if (tid < 32) {
            float a = (tid < 50) ? w3s[tid] * o2[tid] : 0.f;
            if (tid < 18) a += w3s[tid + 32] * o2[tid + 32];
            a = warp_sum(a);
            if (tid == 0) {
                float y = a + b3[0];
                out[b * NS_ + s] = y;
                xs = y;
            }
        }
        __syncthreads();
    }
}

// ---------------------------------------------------------------------------
extern "C" void kernel_launch(void* const* d_in, const int* in_sizes, int n_in,
                              void* d_out, int out_size) {
    const float* x    = (const float*)d_in[0];
    const float* h0   = (const float*)d_in[1];
    const float* c0   = (const float*)d_in[2];
    const float* enc  = (const float*)d_in[3];
    const float* Wa   = (const float*)d_in[4];
    const float* ba   = (const float*)d_in[5];
    const float* Ua   = (const float*)d_in[6];
    const float* bua  = (const float*)d_in[7];
    const float* Va   = (const float*)d_in[8];
    // d_in[9] = bva: constant shift of scores, softmax-invariant -> unused.
    const float* W_ih = (const float*)d_in[10];
    const float* W_hh = (const float*)d_in[11];
    const float* b_ih = (const float*)d_in[12];
    const float* b_hh = (const float*)d_in[13];
    const float* W1   = (const float*)d_in[14];
    const float* b1   = (const float*)d_in[15];
    const float* W2   = (const float*)d_in[16];
    const float* b2   = (const float*)d_in[17];
    const float* W3   = (const float*)d_in[18];
    const float* b3   = (const float*)d_in[19];
    float* out = (float*)d_out;

    const int kg_dsm = (32 * KG_XPAD + 8 * 400) * 4;   // 64,128 B
    cudaFuncSetAttribute(kg_gates, cudaFuncAttributeMaxDynamicSharedMemorySize, kg_dsm);
    cudaFuncSetAttribute(k4_decode, cudaFuncAttributeMaxDynamicSharedMemorySize, K4_DSM);

    k0_qproj<<<B_, 256>>>(h0, Wa, ba, bua);
    k1_scores<<<NTILES, 256>>>(enc, Ua, Va);
    k2_reduce<<<B_, 256>>>();
    kg_gates<<<dim3(B_ / 32, (4 * H_) / 8), 256, kg_dsm>>>(h0, W_ih, W_hh, b_ih, b_hh);
    k4_decode<<<B_, 256, K4_DSM>>>(x, c0, W1, b1, W2, b2, W3, b3, out);
}